// round 17
// baseline (speedup 1.0000x reference)
#include <cuda_runtime.h>
#include <cuda_bf16.h>
#include <cuda_fp16.h>
#include <cstdint>

#define KNBR     16
#define C        128
#define ROWS     32768
#define TM       32              // rows per stage
#define THREADS  384             // warps 0-7 producer, 8-11 consumer
#define NTILES   (ROWS / TM)     // 1024
#define GRID     304             // 2 blocks/SM (exactly resident)

#define SWF_BYTES   65536
#define HSTRIDE_W   68           // u32 words per h row (136 bf16 = 272 B)
#define STAGE_U32   (TM * HSTRIDE_W)
#define STAGE_BYTES (2 * STAGE_U32 * 4)       // 17408
#define SMEM_BYTES  (SWF_BYTES + 2 * STAGE_BYTES + 16)

#define NCVT  (ROWS * C / 8)     // 524288 uint4 conversions

__device__ int    g_tile_ctr = 0;
__device__ int    g_cvt_done = 0;
__device__ int    g_fin      = 0;
__device__ __half g_x16[ROWS * C];            // fp16 mirror of x (8 MB)

typedef unsigned long long u64;

__device__ __forceinline__ u64 add2(u64 a, u64 b) {
    u64 d; asm("add.rn.f32x2 %0, %1, %2;" : "=l"(d) : "l"(a), "l"(b)); return d;
}
__device__ __forceinline__ u64 mul2(u64 a, u64 b) {
    u64 d; asm("mul.rn.f32x2 %0, %1, %2;" : "=l"(d) : "l"(a), "l"(b)); return d;
}
__device__ __forceinline__ u64 rep2(float v) {
    u64 d; asm("mov.b64 %0, {%1, %1};" : "=l"(d) : "f"(v)); return d;
}
__device__ __forceinline__ u64 pack2(float a, float b) {
    u64 d; asm("mov.b64 %0, {%1, %2};" : "=l"(d) : "f"(a), "f"(b)); return d;
}
__device__ __forceinline__ float2 unpack2(u64 v) {
    float2 r; asm("mov.b64 {%0, %1}, %2;" : "=f"(r.x), "=f"(r.y) : "l"(v)); return r;
}
__device__ __forceinline__ u64 h2f2(uint32_t h) {
    __half2 hh = *reinterpret_cast<__half2*>(&h);
    float2 f = __half22float2(hh);
    return pack2(f.x, f.y);
}
__device__ __forceinline__ void hilo2(float a, float b, uint32_t& hi, uint32_t& lo) {
    __nv_bfloat162 h = __floats2bfloat162_rn(a, b);
    float ra = a - __bfloat162float(h.x);
    float rb = b - __bfloat162float(h.y);
    __nv_bfloat162 l = __floats2bfloat162_rn(ra, rb);
    hi = *reinterpret_cast<uint32_t*>(&h);
    lo = *reinterpret_cast<uint32_t*>(&l);
}
__device__ __forceinline__ void mma_bf16(float* c, const uint32_t* a, uint32_t b0, uint32_t b1) {
    asm volatile(
        "mma.sync.aligned.m16n8k16.row.col.f32.bf16.bf16.f32 "
        "{%0,%1,%2,%3}, {%4,%5,%6,%7}, {%8,%9}, {%0,%1,%2,%3};"
        : "+f"(c[0]), "+f"(c[1]), "+f"(c[2]), "+f"(c[3])
        : "r"(a[0]), "r"(a[1]), "r"(a[2]), "r"(a[3]), "r"(b0), "r"(b1));
}
__device__ __forceinline__ void ldsm4(uint32_t* r, uint32_t addr) {
    asm volatile("ldmatrix.sync.aligned.m8n8.x4.shared.b16 {%0,%1,%2,%3}, [%4];"
        : "=r"(r[0]), "=r"(r[1]), "=r"(r[2]), "=r"(r[3]) : "r"(addr));
}
__device__ __forceinline__ uint32_t smem_u32p(const void* p) {
    uint32_t a;
    asm("{ .reg .u64 t; cvta.to.shared.u64 t, %1; cvt.u32.u64 %0, t; }" : "=r"(a) : "l"(p));
    return a;
}
__device__ __forceinline__ void bar_sync(int id) {
    asm volatile("bar.sync %0, 384;" :: "r"(id) : "memory");
}
__device__ __forceinline__ void bar_arrive(int id) {
    asm volatile("bar.arrive %0, 384;" :: "r"(id) : "memory");
}
__device__ __forceinline__ void bar_sync_prod(int id) {
    asm volatile("bar.sync %0, 256;" :: "r"(id) : "memory");
}

__global__ __launch_bounds__(THREADS, 2)
void gin_fused_kernel(const float* __restrict__ x,
                      const void* __restrict__ ei_raw,
                      const float* __restrict__ W,
                      const float* __restrict__ bias,
                      const float* __restrict__ epsp,
                      float* __restrict__ out)
{
    extern __shared__ char smem[];
    uint4*    sWf  = (uint4*)smem;                          // [ks][n][t]
    uint32_t* hbuf = (uint32_t*)(smem + SWF_BYTES);         // 2 stages x (hi | lo)
    volatile int* s_tile = (volatile int*)(smem + SWF_BYTES + 2 * STAGE_BYTES); // 4 slots

    const int tid = threadIdx.x;

    // ============ Phase 0: convert my slice of x -> g_x16 ============
    {
        const float4* src = (const float4*)x;
        for (int i = blockIdx.x * THREADS + tid; i < NCVT; i += GRID * THREADS) {
            float4 a = src[2 * i], b = src[2 * i + 1];
            __half2 h0 = __floats2half2_rn(a.x, a.y);
            __half2 h1 = __floats2half2_rn(a.z, a.w);
            __half2 h2 = __floats2half2_rn(b.x, b.y);
            __half2 h3 = __floats2half2_rn(b.z, b.w);
            uint4 o;
            o.x = *reinterpret_cast<uint32_t*>(&h0);
            o.y = *reinterpret_cast<uint32_t*>(&h1);
            o.z = *reinterpret_cast<uint32_t*>(&h2);
            o.w = *reinterpret_cast<uint32_t*>(&h3);
            reinterpret_cast<uint4*>(g_x16)[i] = o;
        }
        __syncthreads();
        if (tid == 0) { __threadfence(); atomicAdd(&g_cvt_done, 1); }
    }

    // ---------- dtype sniff: int64 (odd words all 0) vs int32 ----------
    const int* w32 = (const int*)ei_raw;
    int orv = 0;
    #pragma unroll
    for (int t = 0; t < 64; t++) orv |= w32[t * 8192 + 1];
    const bool is64 = (orv == 0);
    const long long* w64 = (const long long*)ei_raw;

    // ---------- build W fragments in smem (overlaps other blocks' conversion) ----------
    for (int idx = tid; idx < 4096; idx += THREADS) {
        const int ks = idx >> 9;
        const int n  = (idx >> 2) & 127;
        const int t  = idx & 3;
        const int k0 = 16 * ks + 2 * t;
        const float* wr = W + (size_t)n * C;
        float2 wa = *(const float2*)(wr + k0);
        float2 wb = *(const float2*)(wr + k0 + 8);
        uint4 f;
        hilo2(wa.x, wa.y, f.x, f.z);
        hilo2(wb.x, wb.y, f.y, f.w);
        sWf[idx] = f;
    }

    // ---------- wait for ALL blocks' conversion ----------
    if (tid == 0) {
        while (atomicAdd(&g_cvt_done, 0) < GRID) { }
    }
    __syncthreads();

    const float oe  = 1.0f + epsp[0];
    const u64   oe2 = rep2(oe);

    if (tid < 256) {
        // =================== PRODUCER: warps 0-7 ===================
        const int lrow = tid >> 3;        // 0..31 : row within tile
        const int p    = tid & 7;

        for (int iter = 0;; iter++) {
            const int s    = iter & 1;
            const int slot = iter & 3;
            uint32_t* shi = hbuf + s * (2 * STAGE_U32);
            uint32_t* slo = shi + STAGE_U32;

            if (tid == 0) s_tile[slot] = atomicAdd(&g_tile_ctr, 1);
            bar_sync_prod(5);
            const int tile = s_tile[slot];
            if (tile >= NTILES) { bar_arrive(1 + s); break; }

            const int row = tile * TM + lrow;
            const int bbase = (row >> 13) << 13;   // b * 8192

            // ---- all register work BEFORE the empty-wait ----
            int idxs[KNBR];
            if (!is64) {
                const int4* ip = (const int4*)(w32 + (size_t)row * KNBR);
                #pragma unroll
                for (int q = 0; q < 4; q++) {
                    int4 v = ip[q];
                    idxs[4*q+0] = v.x; idxs[4*q+1] = v.y;
                    idxs[4*q+2] = v.z; idxs[4*q+3] = v.w;
                }
            } else {
                #pragma unroll
                for (int k = 0; k < KNBR; k++)
                    idxs[k] = (int)w64[(size_t)row * KNBR + k];
            }
            #pragma unroll
            for (int k = 0; k < KNBR; k++)
                idxs[k] = (bbase + idxs[k]) << 7;

            const float* xs = x + ((size_t)row << 7);
            u64 a[8];
            {
                float4 v0 = *(const float4*)(xs + 8 * p);
                float4 v1 = *(const float4*)(xs + 8 * p + 4);
                float4 v2 = *(const float4*)(xs + 64 + 8 * p);
                float4 v3 = *(const float4*)(xs + 64 + 8 * p + 4);
                a[0] = mul2(pack2(v0.x, v0.y), oe2);
                a[1] = mul2(pack2(v0.z, v0.w), oe2);
                a[2] = mul2(pack2(v1.x, v1.y), oe2);
                a[3] = mul2(pack2(v1.z, v1.w), oe2);
                a[4] = mul2(pack2(v2.x, v2.y), oe2);
                a[5] = mul2(pack2(v2.z, v2.w), oe2);
                a[6] = mul2(pack2(v3.x, v3.y), oe2);
                a[7] = mul2(pack2(v3.z, v3.w), oe2);
            }

            #pragma unroll 4
            for (int k = 0; k < KNBR; k++) {
                const __half* xn = g_x16 + idxs[k];
                uint4 v0 = *(const uint4*)(xn + 8 * p);
                uint4 v1 = *(const uint4*)(xn + 64 + 8 * p);
                a[0] = add2(a[0], h2f2(v0.x));
                a[1] = add2(a[1], h2f2(v0.y));
                a[2] = add2(a[2], h2f2(v0.z));
                a[3] = add2(a[3], h2f2(v0.w));
                a[4] = add2(a[4], h2f2(v1.x));
                a[5] = add2(a[5], h2f2(v1.y));
                a[6] = add2(a[6], h2f2(v1.z));
                a[7] = add2(a[7], h2f2(v1.w));
            }

            uint32_t hw[8], lw[8];
            #pragma unroll
            for (int q = 0; q < 8; q++) {
                float2 f = unpack2(a[q]);
                hilo2(f.x, f.y, hw[q], lw[q]);
            }

            if (iter >= 2) bar_sync(3 + s);        // stage s consumed?

            const int wbase = lrow * HSTRIDE_W;
            *(uint4*)(shi + wbase + 4 * p)      = make_uint4(hw[0], hw[1], hw[2], hw[3]);
            *(uint4*)(shi + wbase + 32 + 4 * p) = make_uint4(hw[4], hw[5], hw[6], hw[7]);
            *(uint4*)(slo + wbase + 4 * p)      = make_uint4(lw[0], lw[1], lw[2], lw[3]);
            *(uint4*)(slo + wbase + 32 + 4 * p) = make_uint4(lw[4], lw[5], lw[6], lw[7]);

            bar_arrive(1 + s);           // stage s full
        }
    } else {
        // =================== CONSUMER: warps 8-11 ===================
        const int ct   = tid - 256;
        const int w    = ct >> 5;
        const int lane = ct & 31;
        const int g    = lane >> 2;
        const int t    = lane & 3;

        const int lrow  = (lane & 15);
        const int choff = ((lane >> 4) << 4);
        const uint32_t hbase = smem_u32p(hbuf);

        float2 bb[4];
        #pragma unroll
        for (int nfp = 0; nfp < 4; nfp++)
            bb[nfp] = *(const float2*)(bias + 32 * w + 8 * nfp + 2 * t);

        for (int iter = 0;; iter++) {
            const int s    = iter & 1;
            const int slot = iter & 3;
            const uint32_t hi0 = hbase + s * (2 * STAGE_U32 * 4);
            const uint32_t lo0 = hi0 + STAGE_U32 * 4;

            bar_sync(1 + s);             // wait stage full
            const int tile = s_tile[slot];
            if (tile >= NTILES) break;
            const int row0 = tile * TM;

            float acc[2][4][4];
            #pragma unroll
            for (int mt = 0; mt < 2; mt++)
                #pragma unroll
                for (int nfp = 0; nfp < 4; nfp++)
                    #pragma unroll
                    for (int q = 0; q < 4; q++) acc[mt][nfp][q] = 0.f;

            #pragma unroll
            for (int ks = 0; ks < 8; ks++) {
                uint32_t ahi[2][4], alo[2][4];
                #pragma unroll
                for (int mt = 0; mt < 2; mt++) {
                    const uint32_t boff =
                        (uint32_t)((16 * mt + lrow) * 272) + choff + 32 * ks;
                    ldsm4(ahi[mt], hi0 + boff);
                    ldsm4(alo[mt], lo0 + boff);
                }
                #pragma unroll
                for (int nfp = 0; nfp < 4; nfp++) {
                    uint4 f = sWf[ks * 512 + (32 * w + 8 * nfp + g) * 4 + t];
                    #pragma unroll
                    for (int mt = 0; mt < 2; mt++) {
                        mma_bf16(acc[mt][nfp], ahi[mt], f.x, f.y);
                        mma_bf16(acc[mt][nfp], ahi[mt], f.z, f.w);
                        mma_bf16(acc[mt][nfp], alo[mt], f.x, f.y);
                    }
                }
            }
            bar_arrive(3 + s);           // stage free (acc in regs)

            #pragma unroll
            for (int mt = 0; mt < 2; mt++) {
                const int r0 = row0 + 16 * mt + g;
                #pragma unroll
                for (int nfp = 0; nfp < 4; nfp++) {
                    const int col = 32 * w + 8 * nfp + 2 * t;
                    float2 o0, o1;
                    o0.x = fmaxf(acc[mt][nfp][0] + bb[nfp].x, 0.f);
                    o0.y = fmaxf(acc[mt][nfp][1] + bb[nfp].y, 0.f);
                    o1.x = fmaxf(acc[mt][nfp][2] + bb[nfp].x, 0.f);
                    o1.y = fmaxf(acc[mt][nfp][3] + bb[nfp].y, 0.f);
                    *(float2*)(out + (size_t)r0 * C + col)       = o0;
                    *(float2*)(out + (size_t)(r0 + 8) * C + col) = o1;
                }
            }
        }
    }

    // ============ epilogue: last block resets global state for next replay ============
    __syncthreads();
    if (tid == 0) {
        int f = atomicAdd(&g_fin, 1);
        if (f == GRID - 1) {
            g_tile_ctr = 0;
            g_cvt_done = 0;
            g_fin      = 0;
            __threadfence();
        }
    }
}

extern "C" void kernel_launch(void* const* d_in, const int* in_sizes, int n_in,
                              void* d_out, int out_size)
{
    const float* x    = (const float*)d_in[0];
    const void*  ei   = d_in[1];
    const float* W    = (const float*)d_in[2];
    const float* bias = (const float*)d_in[3];
    const float* eps  = (const float*)d_in[4];
    float*       out  = (float*)d_out;

    cudaFuncSetAttribute(gin_fused_kernel,
                         cudaFuncAttributeMaxDynamicSharedMemorySize, SMEM_BYTES);

    gin_fused_kernel<<<GRID, THREADS, SMEM_BYTES>>>(x, ei, W, bias, eps, out);
}